// round 4
// baseline (speedup 1.0000x reference)
#include <cuda_runtime.h>
#include <cuda_bf16.h>
#include <math.h>
#include <stdint.h>

// Problem constants
#define BB 2
#define NN 2048
#define MM 2048
#define DD 1024
#define HH 16
#define HD 64
#define SCALE 0.125f   // 1/sqrt(64)

#define BROW 24        // bf16 smem row stride (16 data + 8 pad) -> conflict-free

typedef __nv_bfloat16 bf16;
typedef __nv_bfloat162 bf162;

// ---------------------------------------------------------------------------
// Scratch (allocation-free rule: __device__ globals)
// ---------------------------------------------------------------------------
#define NELEM_IO ((size_t)BB * NN * DD)   // 4M elements
#define NELEM_W  ((size_t)DD * DD)        // 1M elements

__device__ float g_S[(size_t)BB * HH * NN * MM];   // 512 MB (S, then P in place)
__device__ float g_V[NELEM_IO];                    // 16 MB fp32 (for OV)

// split inputs
__device__ bf16 g_QIh[NELEM_IO], g_QIl[NELEM_IO];
__device__ bf16 g_KIh[NELEM_IO], g_KIl[NELEM_IO];
__device__ bf16 g_VIh[NELEM_IO], g_VIl[NELEM_IO];
// split weights
__device__ bf16 g_WQh[NELEM_W], g_WQl[NELEM_W];
__device__ bf16 g_WKh[NELEM_W], g_WKl[NELEM_W];
__device__ bf16 g_WVh[NELEM_W], g_WVl[NELEM_W];
__device__ bf16 g_WOh[NELEM_W], g_WOl[NELEM_W];
// projected Q/K (hi/lo), attention output O (hi/lo)
__device__ bf16 g_Qh[NELEM_IO], g_Ql[NELEM_IO];
__device__ bf16 g_Kh[NELEM_IO], g_Kl[NELEM_IO];
__device__ bf16 g_Oh[NELEM_IO], g_Ol[NELEM_IO];

// ---------------------------------------------------------------------------
// Helpers
// ---------------------------------------------------------------------------
#define MMA_BF16(d, a0, a1, a2, a3, b0, b1)                                \
    asm volatile("mma.sync.aligned.m16n8k16.row.col.f32.bf16.bf16.f32 "    \
        "{%0,%1,%2,%3}, {%4,%5,%6,%7}, {%8,%9}, {%0,%1,%2,%3};"            \
        : "+f"(d[0]), "+f"(d[1]), "+f"(d[2]), "+f"(d[3])                   \
        : "r"(a0), "r"(a1), "r"(a2), "r"(a3), "r"(b0), "r"(b1))

__device__ __forceinline__ void cp16(uint32_t dst, const void* src) {
    asm volatile("cp.async.ca.shared.global [%0], [%1], 16;" :: "r"(dst), "l"(src));
}
__device__ __forceinline__ void cp_commit() { asm volatile("cp.async.commit_group;"); }
__device__ __forceinline__ void cp_wait1()  { asm volatile("cp.async.wait_group 1;"); }
__device__ __forceinline__ void cp_wait0()  { asm volatile("cp.async.wait_group 0;"); }

__device__ __forceinline__ void split2(float2 v, bf162& hi, bf162& lo) {
    hi = __float22bfloat162_rn(v);
    float2 hf = __bfloat1622float2(hi);
    lo = __float22bfloat162_rn(make_float2(v.x - hf.x, v.y - hf.y));
}

// ---------------------------------------------------------------------------
// Elementwise split: fp32 -> hi/lo bf16
// ---------------------------------------------------------------------------
__global__ __launch_bounds__(256) void split_f32(
    const float4* __restrict__ x, uint2* __restrict__ hi,
    uint2* __restrict__ lo, int n4)
{
    int i = blockIdx.x * 256 + threadIdx.x;
    if (i >= n4) return;
    float4 v = x[i];
    bf162 h01, l01, h23, l23;
    split2(make_float2(v.x, v.y), h01, l01);
    split2(make_float2(v.z, v.w), h23, l23);
    hi[i] = make_uint2(*(uint32_t*)&h01, *(uint32_t*)&h23);
    lo[i] = make_uint2(*(uint32_t*)&l01, *(uint32_t*)&l23);
}

// ---------------------------------------------------------------------------
// Shared 3-term bf16 mainloop: acc += A(128xK) * B(128xK)^T
// smem: [buf][tile: Ah,Al,Bh,Bl][128][BROW] bf16, double buffered.
// Warp tile 64x32 (2m x 4n warps), k-chunk 16.
// ---------------------------------------------------------------------------
__device__ __forceinline__ void mma3_mainloop(
    const bf16* __restrict__ Ah, const bf16* __restrict__ Al, int lda,
    const bf16* __restrict__ Bh, const bf16* __restrict__ Bl, int ldb,
    int kchunks, bf16 (&sm)[2][4][128][BROW],
    float (&acc)[4][4][4], int tid)
{
    const int lane = tid & 31;
    const int warp = tid >> 5;
    const int g = lane >> 2, t = lane & 3;
    const int wm0 = (warp >> 2) * 64;
    const int wn0 = (warp & 3) * 32;

    const int r  = tid >> 1;          // 0..127
    const int hf = tid & 1;           // 0..1 (16B half of 32B row)
    uint32_t s0 = (uint32_t)__cvta_generic_to_shared(&sm[0][0][0][0]);
    const uint32_t tileB = 128 * BROW * 2;
    const uint32_t bufB  = 4 * tileB;
    const uint32_t dst   = (uint32_t)(r * (BROW * 2) + hf * 16);
    const size_t aoff = (size_t)r * lda + hf * 8;
    const size_t boff = (size_t)r * ldb + hf * 8;

    // preload chunk 0 -> buf 0
    cp16(s0 + 0 * tileB + dst, Ah + aoff);
    cp16(s0 + 1 * tileB + dst, Al + aoff);
    cp16(s0 + 2 * tileB + dst, Bh + boff);
    cp16(s0 + 3 * tileB + dst, Bl + boff);
    cp_commit();

    for (int c = 0; c < kchunks; c++) {
        const int buf = c & 1;
        if (c + 1 < kchunks) {
            uint32_t sb = s0 + (buf ^ 1) * bufB;
            int k0 = (c + 1) * 16;
            cp16(sb + 0 * tileB + dst, Ah + aoff + k0);
            cp16(sb + 1 * tileB + dst, Al + aoff + k0);
            cp16(sb + 2 * tileB + dst, Bh + boff + k0);
            cp16(sb + 3 * tileB + dst, Bl + boff + k0);
            cp_commit();
            cp_wait1();
        } else {
            cp_wait0();
        }
        __syncthreads();

        uint32_t ah[4][4], al[4][4];
#pragma unroll
        for (int mt = 0; mt < 4; mt++) {
            int rr = wm0 + mt * 16 + g;
            ah[mt][0] = *(const uint32_t*)&sm[buf][0][rr][2 * t];
            ah[mt][1] = *(const uint32_t*)&sm[buf][0][rr + 8][2 * t];
            ah[mt][2] = *(const uint32_t*)&sm[buf][0][rr][8 + 2 * t];
            ah[mt][3] = *(const uint32_t*)&sm[buf][0][rr + 8][8 + 2 * t];
            al[mt][0] = *(const uint32_t*)&sm[buf][1][rr][2 * t];
            al[mt][1] = *(const uint32_t*)&sm[buf][1][rr + 8][2 * t];
            al[mt][2] = *(const uint32_t*)&sm[buf][1][rr][8 + 2 * t];
            al[mt][3] = *(const uint32_t*)&sm[buf][1][rr + 8][8 + 2 * t];
        }
#pragma unroll
        for (int nt = 0; nt < 4; nt++) {
            int cc = wn0 + nt * 8 + g;
            uint32_t bh0 = *(const uint32_t*)&sm[buf][2][cc][2 * t];
            uint32_t bh1 = *(const uint32_t*)&sm[buf][2][cc][8 + 2 * t];
            uint32_t bl0 = *(const uint32_t*)&sm[buf][3][cc][2 * t];
            uint32_t bl1 = *(const uint32_t*)&sm[buf][3][cc][8 + 2 * t];
#pragma unroll
            for (int mt = 0; mt < 4; mt++) {
                float* d = acc[mt][nt];
                MMA_BF16(d, ah[mt][0], ah[mt][1], ah[mt][2], ah[mt][3], bh0, bh1);
                MMA_BF16(d, ah[mt][0], ah[mt][1], ah[mt][2], ah[mt][3], bl0, bl1);
                MMA_BF16(d, al[mt][0], al[mt][1], al[mt][2], al[mt][3], bh0, bh1);
            }
        }
        __syncthreads();
    }
}

// ---------------------------------------------------------------------------
// Projection GEMM -> hi/lo bf16 output (used for Q, K).
// C = A @ W^T + bias; optional padded-key-row zeroing.
// ---------------------------------------------------------------------------
__global__ __launch_bounds__(256, 2) void proj_bf16out(
    const bf16* __restrict__ Ah, const bf16* __restrict__ Al,
    const bf16* __restrict__ Wh, const bf16* __restrict__ Wl,
    const float* __restrict__ bias,
    bf16* __restrict__ Ch, bf16* __restrict__ Cl,
    const int* __restrict__ pad)
{
    __shared__ bf16 sm[2][4][128][BROW];
    const int tid = threadIdx.x;
    const int m0 = blockIdx.x * 128;
    const int n0 = blockIdx.y * 128;

    float acc[4][4][4];
#pragma unroll
    for (int i = 0; i < 4; i++)
#pragma unroll
        for (int j = 0; j < 4; j++)
#pragma unroll
            for (int q = 0; q < 4; q++) acc[i][j][q] = 0.f;

    mma3_mainloop(Ah + (size_t)m0 * DD, Al + (size_t)m0 * DD, DD,
                  Wh + (size_t)n0 * DD, Wl + (size_t)n0 * DD, DD,
                  64, sm, acc, tid);

    const int lane = tid & 31;
    const int warp = tid >> 5;
    const int g = lane >> 2, t = lane & 3;
    const int wm0 = (warp >> 2) * 64;
    const int wn0 = (warp & 3) * 32;

#pragma unroll
    for (int mt = 0; mt < 4; mt++) {
        int r0 = m0 + wm0 + mt * 16 + g;
        int r1 = r0 + 8;
        bool z0 = false, z1 = false;
        if (pad != nullptr) {
            z0 = ((r0 & 2047) >= MM - pad[r0 >> 11]);
            z1 = ((r1 & 2047) >= MM - pad[r1 >> 11]);
        }
#pragma unroll
        for (int nt = 0; nt < 4; nt++) {
            int col = n0 + wn0 + nt * 8 + 2 * t;
            float2 bi = *(const float2*)&bias[col];
            float* d = acc[mt][nt];
            float2 x0 = z0 ? make_float2(0.f, 0.f)
                           : make_float2(d[0] + bi.x, d[1] + bi.y);
            float2 x1 = z1 ? make_float2(0.f, 0.f)
                           : make_float2(d[2] + bi.x, d[3] + bi.y);
            bf162 h0, l0, h1, l1;
            split2(x0, h0, l0);
            split2(x1, h1, l1);
            *(bf162*)&Ch[(size_t)r0 * DD + col] = h0;
            *(bf162*)&Cl[(size_t)r0 * DD + col] = l0;
            *(bf162*)&Ch[(size_t)r1 * DD + col] = h1;
            *(bf162*)&Cl[(size_t)r1 * DD + col] = l1;
        }
    }
}

// ---------------------------------------------------------------------------
// Projection GEMM -> fp32 output (used for V and final output).
// ---------------------------------------------------------------------------
__global__ __launch_bounds__(256, 2) void proj_f32out(
    const bf16* __restrict__ Ah, const bf16* __restrict__ Al,
    const bf16* __restrict__ Wh, const bf16* __restrict__ Wl,
    const float* __restrict__ bias, float* __restrict__ C)
{
    __shared__ bf16 sm[2][4][128][BROW];
    const int tid = threadIdx.x;
    const int m0 = blockIdx.x * 128;
    const int n0 = blockIdx.y * 128;

    float acc[4][4][4];
#pragma unroll
    for (int i = 0; i < 4; i++)
#pragma unroll
        for (int j = 0; j < 4; j++)
#pragma unroll
            for (int q = 0; q < 4; q++) acc[i][j][q] = 0.f;

    mma3_mainloop(Ah + (size_t)m0 * DD, Al + (size_t)m0 * DD, DD,
                  Wh + (size_t)n0 * DD, Wl + (size_t)n0 * DD, DD,
                  64, sm, acc, tid);

    const int lane = tid & 31;
    const int warp = tid >> 5;
    const int g = lane >> 2, t = lane & 3;
    const int wm0 = (warp >> 2) * 64;
    const int wn0 = (warp & 3) * 32;

#pragma unroll
    for (int mt = 0; mt < 4; mt++) {
        int r0 = m0 + wm0 + mt * 16 + g;
        int r1 = r0 + 8;
#pragma unroll
        for (int nt = 0; nt < 4; nt++) {
            int col = n0 + wn0 + nt * 8 + 2 * t;
            float2 bi = *(const float2*)&bias[col];
            float* d = acc[mt][nt];
            *(float2*)&C[(size_t)r0 * DD + col] = make_float2(d[0] + bi.x, d[1] + bi.y);
            *(float2*)&C[(size_t)r1 * DD + col] = make_float2(d[2] + bi.x, d[3] + bi.y);
        }
    }
}

// ---------------------------------------------------------------------------
// Scores: S[bh,n,m] = (Q[b,n,h,:]·K[b,m,h,:]) * SCALE, 128x128 tiles, K=64.
// Causal: skip tiles fully above the diagonal.
// ---------------------------------------------------------------------------
__global__ __launch_bounds__(256, 2) void scores_mma(const int* __restrict__ flag)
{
    const int mt = blockIdx.x, ntb = blockIdx.y, bh = blockIdx.z;
    if (flag[0] != 0 && mt > ntb) return;

    __shared__ bf16 sm[2][4][128][BROW];
    const int b = bh >> 4, h = bh & 15;
    const int n0 = ntb * 128, m0 = mt * 128;
    const int tid = threadIdx.x;

    float acc[4][4][4];
#pragma unroll
    for (int i = 0; i < 4; i++)
#pragma unroll
        for (int j = 0; j < 4; j++)
#pragma unroll
            for (int q = 0; q < 4; q++) acc[i][j][q] = 0.f;

    const size_t qoff = (size_t)b * NN * DD + (size_t)n0 * DD + h * HD;
    const size_t koff = (size_t)b * MM * DD + (size_t)m0 * DD + h * HD;

    mma3_mainloop(g_Qh + qoff, g_Ql + qoff, DD,
                  g_Kh + koff, g_Kl + koff, DD, 4, sm, acc, tid);

    const int lane = tid & 31;
    const int warp = tid >> 5;
    const int g = lane >> 2, t = lane & 3;
    const int wm0 = (warp >> 2) * 64;   // query-row dir
    const int wn0 = (warp & 3) * 32;    // key-col dir

    float* Sbase = g_S + (size_t)bh * NN * MM;
#pragma unroll
    for (int qt = 0; qt < 4; qt++) {
        int r0 = n0 + wm0 + qt * 16 + g;
        int r1 = r0 + 8;
#pragma unroll
        for (int kt = 0; kt < 4; kt++) {
            int col = m0 + wn0 + kt * 8 + 2 * t;
            float* d = acc[qt][kt];
            *(float2*)&Sbase[(size_t)r0 * MM + col] =
                make_float2(d[0] * SCALE, d[1] * SCALE);
            *(float2*)&Sbase[(size_t)r1 * MM + col] =
                make_float2(d[2] * SCALE, d[3] * SCALE);
        }
    }
}

// ---------------------------------------------------------------------------
// Softmax per row (in place S -> P).
// Causal: only j <= n valid; zero-fill up to the next 128 boundary.
// ---------------------------------------------------------------------------
__global__ __launch_bounds__(256) void attn_softmax(const int* __restrict__ flag)
{
    const int blk = blockIdx.x;            // bh*NN + n
    const int n   = blk & (NN - 1);
    const int causal = (flag[0] != 0);
    const int len    = causal ? (n + 1) : MM;
    const int lenpad = causal ? min((((n >> 7) + 1) << 7), MM) : MM;

    float* row = g_S + (size_t)blk * MM;
    const int tid = threadIdx.x;

    float vals[8];
    int cnt = 0;
    float mx = -3.4e38f;
    for (int j = tid; j < len; j += 256) {
        float s = row[j];
        vals[cnt++] = s;
        mx = fmaxf(mx, s);
    }

    __shared__ float red[8];
#pragma unroll
    for (int o = 16; o > 0; o >>= 1) mx = fmaxf(mx, __shfl_xor_sync(0xffffffffu, mx, o));
    if ((tid & 31) == 0) red[tid >> 5] = mx;
    __syncthreads();
    float bm = red[0];
#pragma unroll
    for (int w = 1; w < 8; w++) bm = fmaxf(bm, red[w]);
    __syncthreads();

    float sum = 0.f;
    for (int i = 0; i < cnt; i++) {
        vals[i] = expf(vals[i] - bm);
        sum += vals[i];
    }
#pragma unroll
    for (int o = 16; o > 0; o >>= 1) sum += __shfl_xor_sync(0xffffffffu, sum, o);
    if ((tid & 31) == 0) red[tid >> 5] = sum;
    __syncthreads();
    float tot = red[0];
#pragma unroll
    for (int w = 1; w < 8; w++) tot += red[w];
    float inv = 1.0f / tot;

    int idx = 0;
    for (int j = tid; j < lenpad; j += 256) {
        float v = (j < len) ? vals[idx++] * inv : 0.f;
        row[j] = v;
    }
}

// ---------------------------------------------------------------------------
// O[b,n,h,:] = sum_j P[bh,n,j] * V[b,j,h,:]  -> hi/lo bf16 output
// Block: 128 query rows x 64 head dims for one (nt, bh). j-tiles of 16.
// ---------------------------------------------------------------------------
__global__ __launch_bounds__(256) void attn_ov(const int* __restrict__ flag)
{
    const int ntb = blockIdx.x, bh = blockIdx.y;
    const int b = bh >> 4, h = bh & 15;
    const int n0 = ntb * 128;
    const int jtmax = (flag[0] != 0) ? ((n0 + 128) >> 4) : (MM >> 4);

    __shared__ float Ps[16][132];   // [j][n], padded
    __shared__ float Vs[16][68];    // [j][d]

    const int tid = threadIdx.x;
    const int tx = tid & 15, ty = tid >> 4;
    const int vr = tid >> 4, vc = (tid & 15) * 4;    // V loader

    const float* Pbase = g_S + ((size_t)bh * NN + n0) * MM;
    const float* Vbase = g_V + (size_t)b * MM * DD + h * HD;

    float acc[8][4];
#pragma unroll
    for (int i = 0; i < 8; i++)
#pragma unroll
        for (int q = 0; q < 4; q++) acc[i][q] = 0.f;

    for (int jt = 0; jt < jtmax; jt++) {
        const int j0 = jt * 16;
#pragma unroll
        for (int it = 0; it < 2; it++) {
            int c = tid + it * 256;          // 0..511
            int r = c >> 2, jc = (c & 3) * 4;
            float4 vp = *(const float4*)&Pbase[(size_t)r * MM + j0 + jc];
            Ps[jc + 0][r] = vp.x; Ps[jc + 1][r] = vp.y;
            Ps[jc + 2][r] = vp.z; Ps[jc + 3][r] = vp.w;
        }
        float4 vv = *(const float4*)&Vbase[(size_t)(j0 + vr) * DD + vc];
        *(float4*)&Vs[vr][vc] = vv;
        __syncthreads();
#pragma unroll
        for (int j = 0; j < 16; j++) {
            float4 v = *(const float4*)&Vs[j][tx * 4];
#pragma unroll
            for (int i = 0; i < 8; i++) {
                float a = Ps[j][ty * 8 + i];
                acc[i][0] += a * v.x;
                acc[i][1] += a * v.y;
                acc[i][2] += a * v.z;
                acc[i][3] += a * v.w;
            }
        }
        __syncthreads();
    }

#pragma unroll
    for (int i = 0; i < 8; i++) {
        size_t off = ((size_t)b * NN + n0 + ty * 8 + i) * DD + h * HD + tx * 4;
        bf162 h01, l01, h23, l23;
        split2(make_float2(acc[i][0], acc[i][1]), h01, l01);
        split2(make_float2(acc[i][2], acc[i][3]), h23, l23);
        *(bf162*)&g_Oh[off]     = h01;
        *(bf162*)&g_Oh[off + 2] = h23;
        *(bf162*)&g_Ol[off]     = l01;
        *(bf162*)&g_Ol[off + 2] = l23;
    }
}

// ---------------------------------------------------------------------------
// wmean[b,n,j] = mean_h P[b,h,n,j]; 0 above the causal diagonal. float4.
// ---------------------------------------------------------------------------
__global__ __launch_bounds__(256) void attn_wmean(const int* __restrict__ flag,
                                                  float* __restrict__ wout)
{
    const int blk = blockIdx.x;            // b*NN + n
    const int b = blk >> 11, n = blk & (NN - 1);
    const int causal = (flag[0] != 0);

    const float* base = g_S + ((size_t)(b * HH) * NN + n) * MM;
    float* orow = wout + (size_t)blk * MM;

    for (int j4 = threadIdx.x * 4; j4 < MM; j4 += 1024) {
        float4 a = make_float4(0.f, 0.f, 0.f, 0.f);
        if (!causal || j4 <= n) {
#pragma unroll
            for (int h = 0; h < HH; h++) {
                float4 v = *(const float4*)&base[(size_t)h * NN * MM + j4];
                a.x += v.x; a.y += v.y; a.z += v.z; a.w += v.w;
            }
            a.x *= (1.0f / HH); a.y *= (1.0f / HH);
            a.z *= (1.0f / HH); a.w *= (1.0f / HH);
            if (causal) {
                if (j4 + 1 > n) a.y = 0.f;
                if (j4 + 2 > n) a.z = 0.f;
                if (j4 + 3 > n) a.w = 0.f;
            }
        }
        *(float4*)&orow[j4] = a;
    }
}

// ---------------------------------------------------------------------------
// Launch
// ---------------------------------------------------------------------------
extern "C" void kernel_launch(void* const* d_in, const int* in_sizes, int n_in,
                              void* d_out, int out_size)
{
    const float* query = (const float*)d_in[0];
    const float* key   = (const float*)d_in[1];
    const float* value = (const float*)d_in[2];
    const int*   kpl   = (const int*)d_in[3];
    const int*   flag  = (const int*)d_in[4];
    const float* wq_w  = (const float*)d_in[5];
    const float* wq_b  = (const float*)d_in[6];
    const float* wk_w  = (const float*)d_in[7];
    const float* wk_b  = (const float*)d_in[8];
    const float* wv_w  = (const float*)d_in[9];
    const float* wv_b  = (const float*)d_in[10];
    const float* wo_w  = (const float*)d_in[11];
    const float* wo_b  = (const float*)d_in[12];
    float* out = (float*)d_out;

    // resolve device-global addresses
    bf16 *QIh, *QIl, *KIh, *KIl, *VIh, *VIl;
    bf16 *WQh, *WQl, *WKh, *WKl, *WVh, *WVl, *WOh, *WOl;
    bf16 *Qh, *Ql, *Kh, *Kl, *Oh, *Ol;
    float *Vp;
    cudaGetSymbolAddress((void**)&QIh, g_QIh); cudaGetSymbolAddress((void**)&QIl, g_QIl);
    cudaGetSymbolAddress((void**)&KIh, g_KIh); cudaGetSymbolAddress((void**)&KIl, g_KIl);
    cudaGetSymbolAddress((void**)&VIh, g_VIh); cudaGetSymbolAddress((void**)&VIl, g_VIl);
    cudaGetSymbolAddress((void**)&WQh, g_WQh); cudaGetSymbolAddress((void**)&WQl, g_WQl);
    cudaGetSymbolAddress((void**)&WKh, g_WKh); cudaGetSymbolAddress((void**)&WKl, g_WKl);
    cudaGetSymbolAddress((void**)&WVh, g_WVh); cudaGetSymbolAddress((void**)&WVl, g_WVl);
    cudaGetSymbolAddress((void**)&WOh, g_WOh); cudaGetSymbolAddress((void**)&WOl, g_WOl);
    cudaGetSymbolAddress((void**)&Qh,  g_Qh);  cudaGetSymbolAddress((void**)&Ql,  g_Ql);
    cudaGetSymbolAddress((void**)&Kh,  g_Kh);  cudaGetSymbolAddress((void**)&Kl,  g_Kl);
    cudaGetSymbolAddress((void**)&Oh,  g_Oh);  cudaGetSymbolAddress((void**)&Ol,  g_Ol);
    cudaGetSymbolAddress((void**)&Vp,  g_V);

    const int n4io = (int)(NELEM_IO / 4);   // 1,048,576
    const int n4w  = (int)(NELEM_W / 4);    // 262,144

    split_f32<<<(n4io + 255) / 256, 256>>>((const float4*)query, (uint2*)QIh, (uint2*)QIl, n4io);
    split_f32<<<(n4io + 255) / 256, 256>>>((const float4*)key,   (uint2*)KIh, (uint2*)KIl, n4io);
    split_f32<<<(n4io + 255) / 256, 256>>>((const float4*)value, (uint2*)VIh, (uint2*)VIl, n4io);
    split_f32<<<(n4w + 255) / 256, 256>>>((const float4*)wq_w, (uint2*)WQh, (uint2*)WQl, n4w);
    split_f32<<<(n4w + 255) / 256, 256>>>((const float4*)wk_w, (uint2*)WKh, (uint2*)WKl, n4w);
    split_f32<<<(n4w + 255) / 256, 256>>>((const float4*)wv_w, (uint2*)WVh, (uint2*)WVl, n4w);
    split_f32<<<(n4w + 255) / 256, 256>>>((const float4*)wo_w, (uint2*)WOh, (uint2*)WOl, n4w);

    const dim3 gProj(32, 8);   // 4096/128 x 1024/128

    proj_bf16out<<<gProj, 256>>>(QIh, QIl, WQh, WQl, wq_b, Qh, Ql, nullptr);
    proj_bf16out<<<gProj, 256>>>(KIh, KIl, WKh, WKl, wk_b, Kh, Kl, kpl);
    proj_f32out <<<gProj, 256>>>(VIh, VIl, WVh, WVl, wv_b, Vp);

    scores_mma  <<<dim3(16, 16, 32), 256>>>(flag);
    attn_softmax<<<BB * HH * NN, 256>>>(flag);
    attn_ov     <<<dim3(16, 32), 256>>>(flag);

    proj_f32out<<<gProj, 256>>>(Oh, Ol, WOh, WOl, wo_b, out);

    const long long need = (long long)BB * NN * DD + (long long)BB * NN * MM;
    if ((long long)out_size >= need)
        attn_wmean<<<BB * NN, 256>>>(flag, out + (size_t)BB * NN * DD);
}

// round 5
// speedup vs baseline: 1.0589x; 1.0589x over previous
#include <cuda_runtime.h>
#include <cuda_bf16.h>
#include <math.h>
#include <stdint.h>

// Problem constants
#define BB 2
#define NN 2048
#define MM 2048
#define DD 1024
#define HH 16
#define HD 64
#define SCALE 0.125f   // 1/sqrt(64)

#define SROW 20        // smem row stride (floats) for 16-wide k tile + pad
#define STAGES 3
#define TILEF (128 * SROW)                 // floats per tile-stage
#define SMEMB (STAGES * 2 * TILEF * 4)     // dynamic smem bytes (61440)

typedef __nv_bfloat16 bf16;
typedef __nv_bfloat162 bf162;

// ---------------------------------------------------------------------------
// Scratch (allocation-free rule: __device__ globals)
// ---------------------------------------------------------------------------
__device__ float g_Q[(size_t)BB * NN * DD];          // 16 MB
__device__ float g_K[(size_t)BB * MM * DD];          // 16 MB
__device__ float g_V[(size_t)BB * MM * DD];          // 16 MB
__device__ float g_O[(size_t)BB * NN * DD];          // 16 MB
__device__ float g_S[(size_t)BB * HH * NN * MM];     // 512 MB (S, then P in place)

// ---------------------------------------------------------------------------
// bf16 3-term split helpers
// ---------------------------------------------------------------------------
__device__ __forceinline__ void split_bf16x2(float2 v, uint32_t& hi, uint32_t& lo) {
    bf162 h = __float22bfloat162_rn(v);
    float2 hf = __bfloat1622float2(h);
    bf162 l = __float22bfloat162_rn(make_float2(v.x - hf.x, v.y - hf.y));
    hi = *(uint32_t*)&h;
    lo = *(uint32_t*)&l;
}

#define MMA_BF16(d, a0, a1, a2, a3, b0, b1)                                \
    asm volatile("mma.sync.aligned.m16n8k16.row.col.f32.bf16.bf16.f32 "    \
        "{%0,%1,%2,%3}, {%4,%5,%6,%7}, {%8,%9}, {%0,%1,%2,%3};"            \
        : "+f"(d[0]), "+f"(d[1]), "+f"(d[2]), "+f"(d[3])                   \
        : "r"(a0), "r"(a1), "r"(a2), "r"(a3), "r"(b0), "r"(b1))

__device__ __forceinline__ void cp16(uint32_t dst, const void* src) {
    asm volatile("cp.async.ca.shared.global [%0], [%1], 16;" :: "r"(dst), "l"(src));
}
__device__ __forceinline__ void cp_commit() { asm volatile("cp.async.commit_group;"); }
__device__ __forceinline__ void cp_wait2()  { asm volatile("cp.async.wait_group 2;"); }
__device__ __forceinline__ void cp_wait1()  { asm volatile("cp.async.wait_group 1;"); }
__device__ __forceinline__ void cp_wait0()  { asm volatile("cp.async.wait_group 0;"); }

// Load one 128x16 fp32 tile into one smem stage.
__device__ __forceinline__ void load_tile16(uint32_t s_base, const float* gsrc,
                                            int ld, int k0, int tid) {
    int r0 = tid >> 2, kc0 = (tid & 3) * 4;
    cp16(s_base + (uint32_t)(r0 * SROW + kc0) * 4, gsrc + (size_t)r0 * ld + k0 + kc0);
    int c1 = tid + 256;
    int r1 = c1 >> 2, kc1 = (c1 & 3) * 4;
    cp16(s_base + (uint32_t)(r1 * SROW + kc1) * 4, gsrc + (size_t)r1 * ld + k0 + kc1);
}

// ---------------------------------------------------------------------------
// Shared 3-term bf16 mainloop (3-stage cp.async pipeline):
// acc[mt][nt][4] += Ablk(128xK) * Bblk(128xK)^T
// sa/sb: fp32 [STAGES][128][SROW]; split to bf16 hi/lo at fragment-load time.
// Warp tile 64x32 (2m x 4n warps), k-chunk 16.
// ---------------------------------------------------------------------------
__device__ __forceinline__ void mma3_mainloop(
    const float* __restrict__ Ab, int lda,
    const float* __restrict__ Bb, int ldb, int ktiles,
    float* sa, float* sb, float (&acc)[4][4][4], int tid)
{
    const int lane = tid & 31;
    const int warp = tid >> 5;
    const int g = lane >> 2, t = lane & 3;
    const int wm0 = (warp >> 2) * 64;
    const int wn0 = (warp & 3) * 32;

    uint32_t sA = (uint32_t)__cvta_generic_to_shared(sa);
    uint32_t sB = (uint32_t)__cvta_generic_to_shared(sb);
    const uint32_t stB = TILEF * 4;

    // preload chunks 0 and 1
    load_tile16(sA, Ab, lda, 0, tid);
    load_tile16(sB, Bb, ldb, 0, tid);
    cp_commit();
    if (ktiles > 1) {
        load_tile16(sA + stB, Ab, lda, 16, tid);
        load_tile16(sB + stB, Bb, ldb, 16, tid);
    }
    cp_commit();

    for (int c = 0; c < ktiles; c++) {
        const int buf = c % 3;
        if (c + 2 < ktiles) {
            uint32_t off = ((c + 2) % 3) * stB;
            load_tile16(sA + off, Ab, lda, (c + 2) * 16, tid);
            load_tile16(sB + off, Bb, ldb, (c + 2) * 16, tid);
            cp_commit();
            cp_wait2();
        } else if (c + 1 < ktiles) {
            cp_wait1();
        } else {
            cp_wait0();
        }
        __syncthreads();

        const float* A3 = sa + buf * TILEF;
        const float* B3 = sb + buf * TILEF;

        uint32_t ah[4][4], al[4][4];
#pragma unroll
        for (int mt = 0; mt < 4; mt++) {
            int rr = wm0 + mt * 16 + g;
            float2 p00 = *(const float2*)&A3[rr * SROW + 2 * t];
            float2 p10 = *(const float2*)&A3[(rr + 8) * SROW + 2 * t];
            float2 p01 = *(const float2*)&A3[rr * SROW + 8 + 2 * t];
            float2 p11 = *(const float2*)&A3[(rr + 8) * SROW + 8 + 2 * t];
            split_bf16x2(p00, ah[mt][0], al[mt][0]);
            split_bf16x2(p10, ah[mt][1], al[mt][1]);
            split_bf16x2(p01, ah[mt][2], al[mt][2]);
            split_bf16x2(p11, ah[mt][3], al[mt][3]);
        }
#pragma unroll
        for (int nt = 0; nt < 4; nt++) {
            int cc = wn0 + nt * 8 + g;
            float2 q0 = *(const float2*)&B3[cc * SROW + 2 * t];
            float2 q1 = *(const float2*)&B3[cc * SROW + 8 + 2 * t];
            uint32_t bh0, bl0, bh1, bl1;
            split_bf16x2(q0, bh0, bl0);
            split_bf16x2(q1, bh1, bl1);
#pragma unroll
            for (int mt = 0; mt < 4; mt++) {
                float* d = acc[mt][nt];
                MMA_BF16(d, ah[mt][0], ah[mt][1], ah[mt][2], ah[mt][3], bh0, bh1);
                MMA_BF16(d, ah[mt][0], ah[mt][1], ah[mt][2], ah[mt][3], bl0, bl1);
                MMA_BF16(d, al[mt][0], al[mt][1], al[mt][2], al[mt][3], bh0, bh1);
            }
        }
        __syncthreads();
    }
}

// Common projection epilogue: add bias, optional pad-zeroing, fp32 store.
__device__ __forceinline__ void proj_epilogue(
    float (&acc)[4][4][4], const float* __restrict__ bias,
    float* __restrict__ C, const int* __restrict__ pad,
    int m0, int n0, int tid)
{
    const int lane = tid & 31;
    const int warp = tid >> 5;
    const int g = lane >> 2, t = lane & 3;
    const int wm0 = (warp >> 2) * 64;
    const int wn0 = (warp & 3) * 32;

#pragma unroll
    for (int mt = 0; mt < 4; mt++) {
        int r0 = m0 + wm0 + mt * 16 + g;
        int r1 = r0 + 8;
        bool z0 = false, z1 = false;
        if (pad != nullptr) {
            z0 = ((r0 & 2047) >= MM - pad[r0 >> 11]);
            z1 = ((r1 & 2047) >= MM - pad[r1 >> 11]);
        }
#pragma unroll
        for (int nt = 0; nt < 4; nt++) {
            int col = n0 + wn0 + nt * 8 + 2 * t;
            float2 bi = *(const float2*)&bias[col];
            float* d = acc[mt][nt];
            float2 o0 = z0 ? make_float2(0.f, 0.f)
                           : make_float2(d[0] + bi.x, d[1] + bi.y);
            float2 o1 = z1 ? make_float2(0.f, 0.f)
                           : make_float2(d[2] + bi.x, d[3] + bi.y);
            *(float2*)&C[(size_t)r0 * DD + col] = o0;
            *(float2*)&C[(size_t)r1 * DD + col] = o1;
        }
    }
}

// ---------------------------------------------------------------------------
// Fused Q/K/V projection: grid (32, 24). Segment = blockIdx.y >> 3.
// ---------------------------------------------------------------------------
__global__ __launch_bounds__(256, 2) void qkv_mma(
    const float* __restrict__ q_in, const float* __restrict__ k_in,
    const float* __restrict__ v_in,
    const float* __restrict__ wq, const float* __restrict__ wk,
    const float* __restrict__ wv,
    const float* __restrict__ bq, const float* __restrict__ bk,
    const float* __restrict__ bv,
    const int* __restrict__ kpl)
{
    extern __shared__ float smem[];
    float* sa = smem;
    float* sb = smem + STAGES * TILEF;

    const int tid = threadIdx.x;
    const int seg = blockIdx.y >> 3;
    const int n0 = (blockIdx.y & 7) * 128;
    const int m0 = blockIdx.x * 128;

    const float* A    = (seg == 0) ? q_in : (seg == 1) ? k_in : v_in;
    const float* W    = (seg == 0) ? wq   : (seg == 1) ? wk   : wv;
    const float* bias = (seg == 0) ? bq   : (seg == 1) ? bk   : bv;
    float*       C    = (seg == 0) ? g_Q  : (seg == 1) ? g_K  : g_V;
    const int*   pad  = (seg == 1) ? kpl  : nullptr;

    float acc[4][4][4];
#pragma unroll
    for (int i = 0; i < 4; i++)
#pragma unroll
        for (int j = 0; j < 4; j++)
#pragma unroll
            for (int p = 0; p < 4; p++) acc[i][j][p] = 0.f;

    mma3_mainloop(A + (size_t)m0 * DD, DD, W + (size_t)n0 * DD, DD,
                  64, sa, sb, acc, tid);
    proj_epilogue(acc, bias, C, pad, m0, n0, tid);
}

// ---------------------------------------------------------------------------
// Output projection: C = A @ W^T + bias. Grid (32, 8).
// ---------------------------------------------------------------------------
__global__ __launch_bounds__(256, 2) void proj_mma(
    const float* __restrict__ A, const float* __restrict__ W,
    const float* __restrict__ bias, float* __restrict__ C)
{
    extern __shared__ float smem[];
    float* sa = smem;
    float* sb = smem + STAGES * TILEF;

    const int tid = threadIdx.x;
    const int m0 = blockIdx.x * 128;
    const int n0 = blockIdx.y * 128;

    float acc[4][4][4];
#pragma unroll
    for (int i = 0; i < 4; i++)
#pragma unroll
        for (int j = 0; j < 4; j++)
#pragma unroll
            for (int p = 0; p < 4; p++) acc[i][j][p] = 0.f;

    mma3_mainloop(A + (size_t)m0 * DD, DD, W + (size_t)n0 * DD, DD,
                  64, sa, sb, acc, tid);
    proj_epilogue(acc, bias, C, nullptr, m0, n0, tid);
}

// ---------------------------------------------------------------------------
// Scores: S[bh,n,m] = (Q[b,n,h,:]·K[b,m,h,:]) * SCALE, 128x128 tiles, K=64.
// Causal: skip tiles fully above the diagonal. Grid (16, 16, 32).
// ---------------------------------------------------------------------------
__global__ __launch_bounds__(256, 2) void scores_mma(const int* __restrict__ flag)
{
    const int mt = blockIdx.x, ntb = blockIdx.y, bh = blockIdx.z;
    if (flag[0] != 0 && mt > ntb) return;

    extern __shared__ float smem[];
    float* sa = smem;
    float* sb = smem + STAGES * TILEF;

    const int b = bh >> 4, h = bh & 15;
    const int n0 = ntb * 128, m0 = mt * 128;
    const int tid = threadIdx.x;

    float acc[4][4][4];
#pragma unroll
    for (int i = 0; i < 4; i++)
#pragma unroll
        for (int j = 0; j < 4; j++)
#pragma unroll
            for (int p = 0; p < 4; p++) acc[i][j][p] = 0.f;

    const float* Ab = g_Q + (size_t)b * NN * DD + (size_t)n0 * DD + h * HD;
    const float* Bb = g_K + (size_t)b * MM * DD + (size_t)m0 * DD + h * HD;

    mma3_mainloop(Ab, DD, Bb, DD, 4, sa, sb, acc, tid);

    const int lane = tid & 31;
    const int warp = tid >> 5;
    const int g = lane >> 2, t = lane & 3;
    const int wm0 = (warp >> 2) * 64;   // query-row dir
    const int wn0 = (warp & 3) * 32;    // key-col dir

    float* Sbase = g_S + (size_t)bh * NN * MM;
#pragma unroll
    for (int qt = 0; qt < 4; qt++) {
        int r0 = n0 + wm0 + qt * 16 + g;
        int r1 = r0 + 8;
#pragma unroll
        for (int kt = 0; kt < 4; kt++) {
            int col = m0 + wn0 + kt * 8 + 2 * t;
            float* d = acc[qt][kt];
            *(float2*)&Sbase[(size_t)r0 * MM + col] =
                make_float2(d[0] * SCALE, d[1] * SCALE);
            *(float2*)&Sbase[(size_t)r1 * MM + col] =
                make_float2(d[2] * SCALE, d[3] * SCALE);
        }
    }
}

// ---------------------------------------------------------------------------
// Softmax per row (in place S -> P).
// Causal: only j <= n valid; zero-fill up to the next 128 boundary.
// ---------------------------------------------------------------------------
__global__ __launch_bounds__(256) void attn_softmax(const int* __restrict__ flag)
{
    const int blk = blockIdx.x;            // bh*NN + n
    const int n   = blk & (NN - 1);
    const int causal = (flag[0] != 0);
    const int len    = causal ? (n + 1) : MM;
    const int lenpad = causal ? min((((n >> 7) + 1) << 7), MM) : MM;

    float* row = g_S + (size_t)blk * MM;
    const int tid = threadIdx.x;

    float vals[8];
    int cnt = 0;
    float mx = -3.4e38f;
    for (int j = tid; j < len; j += 256) {
        float s = row[j];
        vals[cnt++] = s;
        mx = fmaxf(mx, s);
    }

    __shared__ float red[8];
#pragma unroll
    for (int o = 16; o > 0; o >>= 1) mx = fmaxf(mx, __shfl_xor_sync(0xffffffffu, mx, o));
    if ((tid & 31) == 0) red[tid >> 5] = mx;
    __syncthreads();
    float bm = red[0];
#pragma unroll
    for (int w = 1; w < 8; w++) bm = fmaxf(bm, red[w]);
    __syncthreads();

    float sum = 0.f;
    for (int i = 0; i < cnt; i++) {
        vals[i] = expf(vals[i] - bm);
        sum += vals[i];
    }
#pragma unroll
    for (int o = 16; o > 0; o >>= 1) sum += __shfl_xor_sync(0xffffffffu, sum, o);
    if ((tid & 31) == 0) red[tid >> 5] = sum;
    __syncthreads();
    float tot = red[0];
#pragma unroll
    for (int w = 1; w < 8; w++) tot += red[w];
    float inv = 1.0f / tot;

    int idx = 0;
    for (int j = tid; j < lenpad; j += 256) {
        float v = (j < len) ? vals[idx++] * inv : 0.f;
        row[j] = v;
    }
}

// ---------------------------------------------------------------------------
// O[b,n,h,:] = sum_j P[bh,n,j] * V[b,j,h,:]
// Block: 128 query rows x 64 head dims for one (nt, bh). j-tiles of 16.
// ---------------------------------------------------------------------------
__global__ __launch_bounds__(256) void attn_ov(const int* __restrict__ flag)
{
    const int ntb = blockIdx.x, bh = blockIdx.y;
    const int b = bh >> 4, h = bh & 15;
    const int n0 = ntb * 128;
    const int jtmax = (flag[0] != 0) ? ((n0 + 128) >> 4) : (MM >> 4);

    __shared__ float Ps[16][132];   // [j][n], padded
    __shared__ float Vs[16][68];    // [j][d]

    const int tid = threadIdx.x;
    const int tx = tid & 15, ty = tid >> 4;
    const int vr = tid >> 4, vc = (tid & 15) * 4;    // V loader

    const float* Pbase = g_S + ((size_t)bh * NN + n0) * MM;
    const float* Vbase = g_V + (size_t)b * MM * DD + h * HD;

    float acc[8][4];
#pragma unroll
    for (int i = 0; i < 8; i++)
#pragma unroll
        for (int q = 0; q < 4; q++) acc[i][q] = 0.f;

    for (int jt = 0; jt < jtmax; jt++) {
        const int j0 = jt * 16;
#pragma unroll
        for (int it = 0; it < 2; it++) {
            int c = tid + it * 256;          // 0..511
            int r = c >> 2, jc = (c & 3) * 4;
            float4 vp = *(const float4*)&Pbase[(size_t)r * MM + j0 + jc];
            Ps[jc + 0][r] = vp.x; Ps[jc + 1][r] = vp.y;
            Ps[jc + 2][r] = vp.z; Ps[jc + 3][r] = vp.w;
        }
        float4 vv = *(const float4*)&Vbase[(size_t)(j0 + vr) * DD + vc];
        *(float4*)&Vs[vr][vc] = vv;
        __syncthreads();
#pragma unroll
        for (int j = 0; j < 16; j++) {
            float4 v = *(const float4*)&Vs[j][tx * 4];
#pragma unroll
            for (int i = 0; i < 8; i++) {
                float a = Ps[j][ty * 8 + i];
                acc[i][0] += a * v.x;
                acc[i][1] += a * v.y;
                acc[i][2] += a * v.z;
                acc[i][3] += a * v.w;
            }
        }
        __syncthreads();
    }

#pragma unroll
    for (int i = 0; i < 8; i++) {
        float* op = g_O + ((size_t)b * NN + n0 + ty * 8 + i) * DD + h * HD + tx * 4;
        *(float4*)op = make_float4(acc[i][0], acc[i][1], acc[i][2], acc[i][3]);
    }
}

// ---------------------------------------------------------------------------
// wmean[b,n,j] = mean_h P[b,h,n,j]; 0 above the causal diagonal. float4.
// ---------------------------------------------------------------------------
__global__ __launch_bounds__(256) void attn_wmean(const int* __restrict__ flag,
                                                  float* __restrict__ wout)
{
    const int blk = blockIdx.x;            // b*NN + n
    const int b = blk >> 11, n = blk & (NN - 1);
    const int causal = (flag[0] != 0);

    const float* base = g_S + ((size_t)(b * HH) * NN + n) * MM;
    float* orow = wout + (size_t)blk * MM;

    for (int j4 = threadIdx.x * 4; j4 < MM; j4 += 1024) {
        float4 a = make_float4(0.f, 0.f, 0.f, 0.f);
        if (!causal || j4 <= n) {
#pragma unroll
            for (int h = 0; h < HH; h++) {
                float4 v = *(const float4*)&base[(size_t)h * NN * MM + j4];
                a.x += v.x; a.y += v.y; a.z += v.z; a.w += v.w;
            }
            a.x *= (1.0f / HH); a.y *= (1.0f / HH);
            a.z *= (1.0f / HH); a.w *= (1.0f / HH);
            if (causal) {
                if (j4 + 1 > n) a.y = 0.f;
                if (j4 + 2 > n) a.z = 0.f;
                if (j4 + 3 > n) a.w = 0.f;
            }
        }
        *(float4*)&orow[j4] = a;
    }
}

// ---------------------------------------------------------------------------
// Launch
// ---------------------------------------------------------------------------
extern "C" void kernel_launch(void* const* d_in, const int* in_sizes, int n_in,
                              void* d_out, int out_size)
{
    const float* query = (const float*)d_in[0];
    const float* key   = (const float*)d_in[1];
    const float* value = (const float*)d_in[2];
    const int*   kpl   = (const int*)d_in[3];
    const int*   flag  = (const int*)d_in[4];
    const float* wq_w  = (const float*)d_in[5];
    const float* wq_b  = (const float*)d_in[6];
    const float* wk_w  = (const float*)d_in[7];
    const float* wk_b  = (const float*)d_in[8];
    const float* wv_w  = (const float*)d_in[9];
    const float* wv_b  = (const float*)d_in[10];
    const float* wo_w  = (const float*)d_in[11];
    const float* wo_b  = (const float*)d_in[12];
    float* out = (float*)d_out;

    static bool attr_done = false;
    if (!attr_done) {
        cudaFuncSetAttribute(qkv_mma,    cudaFuncAttributeMaxDynamicSharedMemorySize, SMEMB);
        cudaFuncSetAttribute(proj_mma,   cudaFuncAttributeMaxDynamicSharedMemorySize, SMEMB);
        cudaFuncSetAttribute(scores_mma, cudaFuncAttributeMaxDynamicSharedMemorySize, SMEMB);
        attr_done = true;
    }

    float *Op;
    cudaGetSymbolAddress((void**)&Op, g_O);

    qkv_mma<<<dim3(32, 24), 256, SMEMB>>>(query, key, value,
                                          wq_w, wk_w, wv_w,
                                          wq_b, wk_b, wv_b, kpl);

    scores_mma  <<<dim3(16, 16, 32), 256, SMEMB>>>(flag);
    attn_softmax<<<BB * HH * NN, 256>>>(flag);
    attn_ov     <<<dim3(16, 32), 256>>>(flag);

    proj_mma<<<dim3(32, 8), 256, SMEMB>>>(Op, wo_w, wo_b, out);

    const long long need = (long long)BB * NN * DD + (long long)BB * NN * MM;
    if ((long long)out_size >= need)
        attn_wmean<<<BB * NN, 256>>>(flag, out + (size_t)BB * NN * DD);
}

// round 6
// speedup vs baseline: 1.2041x; 1.1371x over previous
#include <cuda_runtime.h>
#include <cuda_bf16.h>
#include <math.h>
#include <stdint.h>

// Problem constants
#define BB 2
#define NN 2048
#define MM 2048
#define DD 1024
#define HH 16
#define HD 64
#define SCALE 0.125f   // 1/sqrt(64)

#define SROW 20        // smem row stride (floats) for 16-wide k tile + pad
#define STAGES 3
#define TILEF (128 * SROW)                 // floats per tile-stage
#define SMEMB (STAGES * 2 * TILEF * 4)     // dynamic smem bytes (61440)

typedef __nv_bfloat16 bf16;
typedef __nv_bfloat162 bf162;

// ---------------------------------------------------------------------------
// Scratch (allocation-free rule: __device__ globals)
// ---------------------------------------------------------------------------
__device__ float g_Q[(size_t)BB * NN * DD];          // 16 MB
__device__ float g_K[(size_t)BB * MM * DD];          // 16 MB
__device__ float g_V[(size_t)BB * MM * DD];          // 16 MB
__device__ float g_O[(size_t)BB * NN * DD];          // 16 MB
__device__ float g_S[(size_t)BB * HH * NN * MM];     // 512 MB (S, then P in place)

// ---------------------------------------------------------------------------
// bf16 3-term split helpers
// ---------------------------------------------------------------------------
__device__ __forceinline__ void split_bf16x2(float2 v, uint32_t& hi, uint32_t& lo) {
    bf162 h = __float22bfloat162_rn(v);
    float2 hf = __bfloat1622float2(h);
    bf162 l = __float22bfloat162_rn(make_float2(v.x - hf.x, v.y - hf.y));
    hi = *(uint32_t*)&h;
    lo = *(uint32_t*)&l;
}

#define MMA_BF16(d, a0, a1, a2, a3, b0, b1)                                \
    asm volatile("mma.sync.aligned.m16n8k16.row.col.f32.bf16.bf16.f32 "    \
        "{%0,%1,%2,%3}, {%4,%5,%6,%7}, {%8,%9}, {%0,%1,%2,%3};"            \
        : "+f"(d[0]), "+f"(d[1]), "+f"(d[2]), "+f"(d[3])                   \
        : "r"(a0), "r"(a1), "r"(a2), "r"(a3), "r"(b0), "r"(b1))

__device__ __forceinline__ void cp16(uint32_t dst, const void* src) {
    asm volatile("cp.async.ca.shared.global [%0], [%1], 16;" :: "r"(dst), "l"(src));
}
__device__ __forceinline__ void cp_commit() { asm volatile("cp.async.commit_group;"); }
__device__ __forceinline__ void cp_wait2()  { asm volatile("cp.async.wait_group 2;"); }
__device__ __forceinline__ void cp_wait1()  { asm volatile("cp.async.wait_group 1;"); }
__device__ __forceinline__ void cp_wait0()  { asm volatile("cp.async.wait_group 0;"); }

// Load one 128x16 fp32 tile into one smem stage.
__device__ __forceinline__ void load_tile16(uint32_t s_base, const float* gsrc,
                                            int ld, int k0, int tid) {
    int r0 = tid >> 2, kc0 = (tid & 3) * 4;
    cp16(s_base + (uint32_t)(r0 * SROW + kc0) * 4, gsrc + (size_t)r0 * ld + k0 + kc0);
    int c1 = tid + 256;
    int r1 = c1 >> 2, kc1 = (c1 & 3) * 4;
    cp16(s_base + (uint32_t)(r1 * SROW + kc1) * 4, gsrc + (size_t)r1 * ld + k0 + kc1);
}

// ---------------------------------------------------------------------------
// Shared 3-term bf16 mainloop (3-stage cp.async pipeline):
// acc[mt][nt][4] += Ablk(128xK) * Bblk(128xK)^T
// sa/sb: fp32 [STAGES][128][SROW]; split to bf16 hi/lo at fragment-load time.
// Warp tile 64x32 (2m x 4n warps), k-chunk 16.
// ---------------------------------------------------------------------------
__device__ __forceinline__ void mma3_mainloop(
    const float* __restrict__ Ab, int lda,
    const float* __restrict__ Bb, int ldb, int ktiles,
    float* sa, float* sb, float (&acc)[4][4][4], int tid)
{
    const int lane = tid & 31;
    const int warp = tid >> 5;
    const int g = lane >> 2, t = lane & 3;
    const int wm0 = (warp >> 2) * 64;
    const int wn0 = (warp & 3) * 32;

    uint32_t sA = (uint32_t)__cvta_generic_to_shared(sa);
    uint32_t sB = (uint32_t)__cvta_generic_to_shared(sb);
    const uint32_t stB = TILEF * 4;

    // preload chunks 0 and 1
    load_tile16(sA, Ab, lda, 0, tid);
    load_tile16(sB, Bb, ldb, 0, tid);
    cp_commit();
    if (ktiles > 1) {
        load_tile16(sA + stB, Ab, lda, 16, tid);
        load_tile16(sB + stB, Bb, ldb, 16, tid);
    }
    cp_commit();

    for (int c = 0; c < ktiles; c++) {
        const int buf = c % 3;
        if (c + 2 < ktiles) {
            uint32_t off = ((c + 2) % 3) * stB;
            load_tile16(sA + off, Ab, lda, (c + 2) * 16, tid);
            load_tile16(sB + off, Bb, ldb, (c + 2) * 16, tid);
            cp_commit();
            cp_wait2();
        } else if (c + 1 < ktiles) {
            cp_wait1();
        } else {
            cp_wait0();
        }
        __syncthreads();

        const float* A3 = sa + buf * TILEF;
        const float* B3 = sb + buf * TILEF;

        uint32_t ah[4][4], al[4][4];
#pragma unroll
        for (int mt = 0; mt < 4; mt++) {
            int rr = wm0 + mt * 16 + g;
            float2 p00 = *(const float2*)&A3[rr * SROW + 2 * t];
            float2 p10 = *(const float2*)&A3[(rr + 8) * SROW + 2 * t];
            float2 p01 = *(const float2*)&A3[rr * SROW + 8 + 2 * t];
            float2 p11 = *(const float2*)&A3[(rr + 8) * SROW + 8 + 2 * t];
            split_bf16x2(p00, ah[mt][0], al[mt][0]);
            split_bf16x2(p10, ah[mt][1], al[mt][1]);
            split_bf16x2(p01, ah[mt][2], al[mt][2]);
            split_bf16x2(p11, ah[mt][3], al[mt][3]);
        }
#pragma unroll
        for (int nt = 0; nt < 4; nt++) {
            int cc = wn0 + nt * 8 + g;
            float2 q0 = *(const float2*)&B3[cc * SROW + 2 * t];
            float2 q1 = *(const float2*)&B3[cc * SROW + 8 + 2 * t];
            uint32_t bh0, bl0, bh1, bl1;
            split_bf16x2(q0, bh0, bl0);
            split_bf16x2(q1, bh1, bl1);
#pragma unroll
            for (int mt = 0; mt < 4; mt++) {
                float* d = acc[mt][nt];
                MMA_BF16(d, ah[mt][0], ah[mt][1], ah[mt][2], ah[mt][3], bh0, bh1);
                MMA_BF16(d, ah[mt][0], ah[mt][1], ah[mt][2], ah[mt][3], bl0, bl1);
                MMA_BF16(d, al[mt][0], al[mt][1], al[mt][2], al[mt][3], bh0, bh1);
            }
        }
        __syncthreads();
    }
}

// Common projection epilogue: add bias, optional pad-zeroing, fp32 store.
__device__ __forceinline__ void proj_epilogue(
    float (&acc)[4][4][4], const float* __restrict__ bias,
    float* __restrict__ C, const int* __restrict__ pad,
    int m0, int n0, int tid)
{
    const int lane = tid & 31;
    const int warp = tid >> 5;
    const int g = lane >> 2, t = lane & 3;
    const int wm0 = (warp >> 2) * 64;
    const int wn0 = (warp & 3) * 32;

#pragma unroll
    for (int mt = 0; mt < 4; mt++) {
        int r0 = m0 + wm0 + mt * 16 + g;
        int r1 = r0 + 8;
        bool z0 = false, z1 = false;
        if (pad != nullptr) {
            z0 = ((r0 & 2047) >= MM - pad[r0 >> 11]);
            z1 = ((r1 & 2047) >= MM - pad[r1 >> 11]);
        }
#pragma unroll
        for (int nt = 0; nt < 4; nt++) {
            int col = n0 + wn0 + nt * 8 + 2 * t;
            float2 bi = *(const float2*)&bias[col];
            float* d = acc[mt][nt];
            float2 o0 = z0 ? make_float2(0.f, 0.f)
                           : make_float2(d[0] + bi.x, d[1] + bi.y);
            float2 o1 = z1 ? make_float2(0.f, 0.f)
                           : make_float2(d[2] + bi.x, d[3] + bi.y);
            *(float2*)&C[(size_t)r0 * DD + col] = o0;
            *(float2*)&C[(size_t)r1 * DD + col] = o1;
        }
    }
}

// ---------------------------------------------------------------------------
// Fused Q/K/V projection: grid (32, 24). Segment = blockIdx.y >> 3.
// ---------------------------------------------------------------------------
__global__ __launch_bounds__(256, 2) void qkv_mma(
    const float* __restrict__ q_in, const float* __restrict__ k_in,
    const float* __restrict__ v_in,
    const float* __restrict__ wq, const float* __restrict__ wk,
    const float* __restrict__ wv,
    const float* __restrict__ bq, const float* __restrict__ bk,
    const float* __restrict__ bv,
    const int* __restrict__ kpl)
{
    extern __shared__ float smem[];
    float* sa = smem;
    float* sb = smem + STAGES * TILEF;

    const int tid = threadIdx.x;
    const int seg = blockIdx.y >> 3;
    const int n0 = (blockIdx.y & 7) * 128;
    const int m0 = blockIdx.x * 128;

    const float* A    = (seg == 0) ? q_in : (seg == 1) ? k_in : v_in;
    const float* W    = (seg == 0) ? wq   : (seg == 1) ? wk   : wv;
    const float* bias = (seg == 0) ? bq   : (seg == 1) ? bk   : bv;
    float*       C    = (seg == 0) ? g_Q  : (seg == 1) ? g_K  : g_V;
    const int*   pad  = (seg == 1) ? kpl  : nullptr;

    float acc[4][4][4];
#pragma unroll
    for (int i = 0; i < 4; i++)
#pragma unroll
        for (int j = 0; j < 4; j++)
#pragma unroll
            for (int p = 0; p < 4; p++) acc[i][j][p] = 0.f;

    mma3_mainloop(A + (size_t)m0 * DD, DD, W + (size_t)n0 * DD, DD,
                  64, sa, sb, acc, tid);
    proj_epilogue(acc, bias, C, pad, m0, n0, tid);
}

// ---------------------------------------------------------------------------
// Output projection: C = A @ W^T + bias. Grid (32, 8).
// ---------------------------------------------------------------------------
__global__ __launch_bounds__(256, 2) void proj_mma(
    const float* __restrict__ A, const float* __restrict__ W,
    const float* __restrict__ bias, float* __restrict__ C)
{
    extern __shared__ float smem[];
    float* sa = smem;
    float* sb = smem + STAGES * TILEF;

    const int tid = threadIdx.x;
    const int m0 = blockIdx.x * 128;
    const int n0 = blockIdx.y * 128;

    float acc[4][4][4];
#pragma unroll
    for (int i = 0; i < 4; i++)
#pragma unroll
        for (int j = 0; j < 4; j++)
#pragma unroll
            for (int p = 0; p < 4; p++) acc[i][j][p] = 0.f;

    mma3_mainloop(A + (size_t)m0 * DD, DD, W + (size_t)n0 * DD, DD,
                  64, sa, sb, acc, tid);
    proj_epilogue(acc, bias, C, nullptr, m0, n0, tid);
}

// ---------------------------------------------------------------------------
// Scores: S[bh,n,m] = (Q[b,n,h,:]·K[b,m,h,:]) * SCALE, 128x128 tiles, K=64.
// Causal: skip tiles fully above the diagonal. Grid (16, 16, 32).
// ---------------------------------------------------------------------------
__global__ __launch_bounds__(256, 2) void scores_mma(const int* __restrict__ flag)
{
    const int mt = blockIdx.x, ntb = blockIdx.y, bh = blockIdx.z;
    if (flag[0] != 0 && mt > ntb) return;

    extern __shared__ float smem[];
    float* sa = smem;
    float* sb = smem + STAGES * TILEF;

    const int b = bh >> 4, h = bh & 15;
    const int n0 = ntb * 128, m0 = mt * 128;
    const int tid = threadIdx.x;

    float acc[4][4][4];
#pragma unroll
    for (int i = 0; i < 4; i++)
#pragma unroll
        for (int j = 0; j < 4; j++)
#pragma unroll
            for (int p = 0; p < 4; p++) acc[i][j][p] = 0.f;

    const float* Ab = g_Q + (size_t)b * NN * DD + (size_t)n0 * DD + h * HD;
    const float* Bb = g_K + (size_t)b * MM * DD + (size_t)m0 * DD + h * HD;

    mma3_mainloop(Ab, DD, Bb, DD, 4, sa, sb, acc, tid);

    const int lane = tid & 31;
    const int warp = tid >> 5;
    const int g = lane >> 2, t = lane & 3;
    const int wm0 = (warp >> 2) * 64;   // query-row dir
    const int wn0 = (warp & 3) * 32;    // key-col dir

    float* Sbase = g_S + (size_t)bh * NN * MM;
#pragma unroll
    for (int qt = 0; qt < 4; qt++) {
        int r0 = n0 + wm0 + qt * 16 + g;
        int r1 = r0 + 8;
#pragma unroll
        for (int kt = 0; kt < 4; kt++) {
            int col = m0 + wn0 + kt * 8 + 2 * t;
            float* d = acc[qt][kt];
            *(float2*)&Sbase[(size_t)r0 * MM + col] =
                make_float2(d[0] * SCALE, d[1] * SCALE);
            *(float2*)&Sbase[(size_t)r1 * MM + col] =
                make_float2(d[2] * SCALE, d[3] * SCALE);
        }
    }
}

// ---------------------------------------------------------------------------
// Softmax per row (in place S -> P).
// Causal: only j <= n valid; zero-fill up to the next 128 boundary.
// ---------------------------------------------------------------------------
__global__ __launch_bounds__(256) void attn_softmax(const int* __restrict__ flag)
{
    const int blk = blockIdx.x;            // bh*NN + n
    const int n   = blk & (NN - 1);
    const int causal = (flag[0] != 0);
    const int len    = causal ? (n + 1) : MM;
    const int lenpad = causal ? min((((n >> 7) + 1) << 7), MM) : MM;

    float* row = g_S + (size_t)blk * MM;
    const int tid = threadIdx.x;

    float vals[8];
    int cnt = 0;
    float mx = -3.4e38f;
    for (int j = tid; j < len; j += 256) {
        float s = row[j];
        vals[cnt++] = s;
        mx = fmaxf(mx, s);
    }

    __shared__ float red[8];
#pragma unroll
    for (int o = 16; o > 0; o >>= 1) mx = fmaxf(mx, __shfl_xor_sync(0xffffffffu, mx, o));
    if ((tid & 31) == 0) red[tid >> 5] = mx;
    __syncthreads();
    float bm = red[0];
#pragma unroll
    for (int w = 1; w < 8; w++) bm = fmaxf(bm, red[w]);
    __syncthreads();

    float sum = 0.f;
    for (int i = 0; i < cnt; i++) {
        vals[i] = expf(vals[i] - bm);
        sum += vals[i];
    }
#pragma unroll
    for (int o = 16; o > 0; o >>= 1) sum += __shfl_xor_sync(0xffffffffu, sum, o);
    if ((tid & 31) == 0) red[tid >> 5] = sum;
    __syncthreads();
    float tot = red[0];
#pragma unroll
    for (int w = 1; w < 8; w++) tot += red[w];
    float inv = 1.0f / tot;

    int idx = 0;
    for (int j = tid; j < lenpad; j += 256) {
        float v = (j < len) ? vals[idx++] * inv : 0.f;
        row[j] = v;
    }
}

// ---------------------------------------------------------------------------
// OV on tensor cores: O[b,n0+0..127, h*64..] = P[bh, n0.., :] @ V[b, :, h*64..]
// Block 128(n) x 64(d), 8 warps as 4(n) x 2(d), warp tile 32n x 32d.
// k = j chunks of 16, double-buffered cp.async. P zero-padded to 128-boundary
// by softmax, so causal extent rounds up to n0+128.
// B fragments gathered from natural-layout V tile (verified conflict-free).
// ---------------------------------------------------------------------------
__global__ __launch_bounds__(256) void attn_ov(const int* __restrict__ flag)
{
    const int ntb = blockIdx.x, bh = blockIdx.y;
    const int b = bh >> 4, h = bh & 15;
    const int n0 = ntb * 128;
    const int chunks = (flag[0] != 0) ? ((n0 + 128) >> 4) : (MM >> 4);

    __shared__ float Ps[2][128][SROW];   // P tile [n][j], fp32
    __shared__ float Vs[2][16][68];      // V tile [j][d], fp32, padded

    const int tid = threadIdx.x;
    const int lane = tid & 31, warp = tid >> 5;
    const int g = lane >> 2, t = lane & 3;
    const int wy = warp >> 1;            // n-dir: 0..3 (32 rows each)
    const int wx = warp & 1;             // d-dir: 0..1 (32 cols each)

    const float* Pbase = g_S + ((size_t)bh * NN + n0) * MM;
    const float* Vbase = g_V + (size_t)b * MM * DD + h * HD;

    uint32_t sP = (uint32_t)__cvta_generic_to_shared(&Ps[0][0][0]);
    uint32_t sV = (uint32_t)__cvta_generic_to_shared(&Vs[0][0][0]);
    const uint32_t PstB = 128 * SROW * 4;
    const uint32_t VstB = 16 * 68 * 4;

    // loaders
    const int pr0 = tid >> 2,          pk0 = (tid & 3) * 4;
    const int pr1 = (tid + 256) >> 2,  pk1 = ((tid + 256) & 3) * 4;
    const int vrr = tid >> 4,          vcc = (tid & 15) * 4;

    float acc[2][4][4];
#pragma unroll
    for (int i = 0; i < 2; i++)
#pragma unroll
        for (int j = 0; j < 4; j++)
#pragma unroll
            for (int p = 0; p < 4; p++) acc[i][j][p] = 0.f;

    // preload chunk 0
    cp16(sP + (uint32_t)(pr0 * SROW + pk0) * 4, Pbase + (size_t)pr0 * MM + pk0);
    cp16(sP + (uint32_t)(pr1 * SROW + pk1) * 4, Pbase + (size_t)pr1 * MM + pk1);
    cp16(sV + (uint32_t)(vrr * 68 + vcc) * 4,   Vbase + (size_t)vrr * DD + vcc);
    cp_commit();

    for (int c = 0; c < chunks; c++) {
        const int buf = c & 1;
        if (c + 1 < chunks) {
            const int j0 = (c + 1) * 16;
            uint32_t op = (buf ^ 1) * PstB;
            uint32_t ov = (buf ^ 1) * VstB;
            cp16(sP + op + (uint32_t)(pr0 * SROW + pk0) * 4, Pbase + (size_t)pr0 * MM + j0 + pk0);
            cp16(sP + op + (uint32_t)(pr1 * SROW + pk1) * 4, Pbase + (size_t)pr1 * MM + j0 + pk1);
            cp16(sV + ov + (uint32_t)(vrr * 68 + vcc) * 4,   Vbase + (size_t)(j0 + vrr) * DD + vcc);
            cp_commit();
            cp_wait1();
        } else {
            cp_wait0();
        }
        __syncthreads();

        // A (P) fragments
        uint32_t ah[2][4], al[2][4];
#pragma unroll
        for (int mt = 0; mt < 2; mt++) {
            int rr = wy * 32 + mt * 16 + g;
            float2 p00 = *(const float2*)&Ps[buf][rr][2 * t];
            float2 p10 = *(const float2*)&Ps[buf][rr + 8][2 * t];
            float2 p01 = *(const float2*)&Ps[buf][rr][8 + 2 * t];
            float2 p11 = *(const float2*)&Ps[buf][rr + 8][8 + 2 * t];
            split_bf16x2(p00, ah[mt][0], al[mt][0]);
            split_bf16x2(p10, ah[mt][1], al[mt][1]);
            split_bf16x2(p01, ah[mt][2], al[mt][2]);
            split_bf16x2(p11, ah[mt][3], al[mt][3]);
        }
        // B (V) fragments: gather k-pairs along j from natural layout
#pragma unroll
        for (int nt = 0; nt < 4; nt++) {
            int dd = wx * 32 + nt * 8 + g;
            float2 q0 = make_float2(Vs[buf][2 * t][dd],     Vs[buf][2 * t + 1][dd]);
            float2 q1 = make_float2(Vs[buf][8 + 2 * t][dd], Vs[buf][9 + 2 * t][dd]);
            uint32_t bh0, bl0, bh1, bl1;
            split_bf16x2(q0, bh0, bl0);
            split_bf16x2(q1, bh1, bl1);
#pragma unroll
            for (int mt = 0; mt < 2; mt++) {
                float* d = acc[mt][nt];
                MMA_BF16(d, ah[mt][0], ah[mt][1], ah[mt][2], ah[mt][3], bh0, bh1);
                MMA_BF16(d, ah[mt][0], ah[mt][1], ah[mt][2], ah[mt][3], bl0, bl1);
                MMA_BF16(d, al[mt][0], al[mt][1], al[mt][2], al[mt][3], bh0, bh1);
            }
        }
        __syncthreads();
    }

    // epilogue: O[n][h*64 + d]
#pragma unroll
    for (int mt = 0; mt < 2; mt++) {
        int r0 = n0 + wy * 32 + mt * 16 + g;
        int r1 = r0 + 8;
#pragma unroll
        for (int nt = 0; nt < 4; nt++) {
            int col = h * HD + wx * 32 + nt * 8 + 2 * t;
            float* d = acc[mt][nt];
            *(float2*)&g_O[((size_t)b * NN + r0) * DD + col] = make_float2(d[0], d[1]);
            *(float2*)&g_O[((size_t)b * NN + r1) * DD + col] = make_float2(d[2], d[3]);
        }
    }
}

// ---------------------------------------------------------------------------
// wmean[b,n,j] = mean_h P[b,h,n,j]; 0 above the causal diagonal. float4.
// ---------------------------------------------------------------------------
__global__ __launch_bounds__(256) void attn_wmean(const int* __restrict__ flag,
                                                  float* __restrict__ wout)
{
    const int blk = blockIdx.x;            // b*NN + n
    const int b = blk >> 11, n = blk & (NN - 1);
    const int causal = (flag[0] != 0);

    const float* base = g_S + ((size_t)(b * HH) * NN + n) * MM;
    float* orow = wout + (size_t)blk * MM;

    for (int j4 = threadIdx.x * 4; j4 < MM; j4 += 1024) {
        float4 a = make_float4(0.f, 0.f, 0.f, 0.f);
        if (!causal || j4 <= n) {
#pragma unroll
            for (int h = 0; h < HH; h++) {
                float4 v = *(const float4*)&base[(size_t)h * NN * MM + j4];
                a.x += v.x; a.y += v.y; a.z += v.z; a.w += v.w;
            }
            a.x *= (1.0f / HH); a.y *= (1.0f / HH);
            a.z *= (1.0f / HH); a.w *= (1.0f / HH);
            if (causal) {
                if (j4 + 1 > n) a.y = 0.f;
                if (j4 + 2 > n) a.z = 0.f;
                if (j4 + 3 > n) a.w = 0.f;
            }
        }
        *(float4*)&orow[j4] = a;
    }
}

// ---------------------------------------------------------------------------
// Launch
// ---------------------------------------------------------------------------
extern "C" void kernel_launch(void* const* d_in, const int* in_sizes, int n_in,
                              void* d_out, int out_size)
{
    const float* query = (const float*)d_in[0];
    const float* key   = (const float*)d_in[1];
    const float* value = (const float*)d_in[2];
    const int*   kpl   = (const int*)d_in[3];
    const int*   flag  = (const int*)d_in[4];
    const float* wq_w  = (const float*)d_in[5];
    const float* wq_b  = (const float*)d_in[6];
    const float* wk_w  = (const float*)d_in[7];
    const float* wk_b  = (const float*)d_in[8];
    const float* wv_w  = (const float*)d_in[9];
    const float* wv_b  = (const float*)d_in[10];
    const float* wo_w  = (const float*)d_in[11];
    const float* wo_b  = (const float*)d_in[12];
    float* out = (float*)d_out;

    static bool attr_done = false;
    if (!attr_done) {
        cudaFuncSetAttribute(qkv_mma,    cudaFuncAttributeMaxDynamicSharedMemorySize, SMEMB);
        cudaFuncSetAttribute(proj_mma,   cudaFuncAttributeMaxDynamicSharedMemorySize, SMEMB);
        cudaFuncSetAttribute(scores_mma, cudaFuncAttributeMaxDynamicSharedMemorySize, SMEMB);
        attr_done = true;
    }

    float *Op;
    cudaGetSymbolAddress((void**)&Op, g_O);

    qkv_mma<<<dim3(32, 24), 256, SMEMB>>>(query, key, value,
                                          wq_w, wk_w, wv_w,
                                          wq_b, wk_b, wv_b, kpl);

    scores_mma  <<<dim3(16, 16, 32), 256, SMEMB>>>(flag);
    attn_softmax<<<BB * HH * NN, 256>>>(flag);
    attn_ov     <<<dim3(16, 32), 256>>>(flag);

    proj_mma<<<dim3(32, 8), 256, SMEMB>>>(Op, wo_w, wo_b, out);

    const long long need = (long long)BB * NN * DD + (long long)BB * NN * MM;
    if ((long long)out_size >= need)
        attn_wmean<<<BB * NN, 256>>>(flag, out + (size_t)BB * NN * DD);
}

// round 9
// speedup vs baseline: 1.2993x; 1.0791x over previous
#include <cuda_runtime.h>
#include <cuda_bf16.h>
#include <math.h>
#include <stdint.h>

// Problem constants
#define BB 2
#define NN 2048
#define MM 2048
#define DD 1024
#define HH 16
#define HD 64
#define SCALE 0.125f   // 1/sqrt(64)

#define SROW 20        // smem row stride (floats) for 16-wide k tile + pad
#define STAGES 3
#define TILEF (128 * SROW)                 // floats per tile-stage
#define SMEMB (STAGES * 2 * TILEF * 4)     // dynamic smem bytes (61440)

typedef __nv_bfloat16 bf16;
typedef __nv_bfloat162 bf162;

// ---------------------------------------------------------------------------
// Scratch (allocation-free rule: __device__ globals)
// ---------------------------------------------------------------------------
__device__ float g_Q[(size_t)BB * NN * DD];          // 16 MB
__device__ float g_K[(size_t)BB * MM * DD];          // 16 MB
__device__ float g_V[(size_t)BB * MM * DD];          // 16 MB
__device__ float g_O[(size_t)BB * NN * DD];          // 16 MB
__device__ float g_S[(size_t)BB * HH * NN * MM];     // 512 MB (S, then P in place)

// ---------------------------------------------------------------------------
// bf16 3-term split helpers
// ---------------------------------------------------------------------------
__device__ __forceinline__ void split_bf16x2(float2 v, uint32_t& hi, uint32_t& lo) {
    bf162 h = __float22bfloat162_rn(v);
    float2 hf = __bfloat1622float2(h);
    bf162 l = __float22bfloat162_rn(make_float2(v.x - hf.x, v.y - hf.y));
    hi = *(uint32_t*)&h;
    lo = *(uint32_t*)&l;
}

#define MMA_BF16(d, a0, a1, a2, a3, b0, b1)                                \
    asm volatile("mma.sync.aligned.m16n8k16.row.col.f32.bf16.bf16.f32 "    \
        "{%0,%1,%2,%3}, {%4,%5,%6,%7}, {%8,%9}, {%0,%1,%2,%3};"            \
        : "+f"(d[0]), "+f"(d[1]), "+f"(d[2]), "+f"(d[3])                   \
        : "r"(a0), "r"(a1), "r"(a2), "r"(a3), "r"(b0), "r"(b1))

__device__ __forceinline__ void cp16(uint32_t dst, const void* src) {
    asm volatile("cp.async.ca.shared.global [%0], [%1], 16;" :: "r"(dst), "l"(src));
}
__device__ __forceinline__ void cp_commit() { asm volatile("cp.async.commit_group;"); }
__device__ __forceinline__ void cp_wait2()  { asm volatile("cp.async.wait_group 2;"); }
__device__ __forceinline__ void cp_wait1()  { asm volatile("cp.async.wait_group 1;"); }
__device__ __forceinline__ void cp_wait0()  { asm volatile("cp.async.wait_group 0;"); }

// Load one 128x16 fp32 tile into one smem stage.
__device__ __forceinline__ void load_tile16(uint32_t s_base, const float* gsrc,
                                            int ld, int k0, int tid) {
    int r0 = tid >> 2, kc0 = (tid & 3) * 4;
    cp16(s_base + (uint32_t)(r0 * SROW + kc0) * 4, gsrc + (size_t)r0 * ld + k0 + kc0);
    int c1 = tid + 256;
    int r1 = c1 >> 2, kc1 = (c1 & 3) * 4;
    cp16(s_base + (uint32_t)(r1 * SROW + kc1) * 4, gsrc + (size_t)r1 * ld + k0 + kc1);
}

// ---------------------------------------------------------------------------
// Shared 3-term bf16 mainloop (3-stage cp.async pipeline):
// acc[mt][nt][4] += Ablk(128xK) * Bblk(128xK)^T
// ---------------------------------------------------------------------------
__device__ __forceinline__ void mma3_mainloop(
    const float* __restrict__ Ab, int lda,
    const float* __restrict__ Bb, int ldb, int ktiles,
    float* sa, float* sb, float (&acc)[4][4][4], int tid)
{
    const int lane = tid & 31;
    const int warp = tid >> 5;
    const int g = lane >> 2, t = lane & 3;
    const int wm0 = (warp >> 2) * 64;
    const int wn0 = (warp & 3) * 32;

    uint32_t sA = (uint32_t)__cvta_generic_to_shared(sa);
    uint32_t sB = (uint32_t)__cvta_generic_to_shared(sb);
    const uint32_t stB = TILEF * 4;

    load_tile16(sA, Ab, lda, 0, tid);
    load_tile16(sB, Bb, ldb, 0, tid);
    cp_commit();
    if (ktiles > 1) {
        load_tile16(sA + stB, Ab, lda, 16, tid);
        load_tile16(sB + stB, Bb, ldb, 16, tid);
    }
    cp_commit();

    for (int c = 0; c < ktiles; c++) {
        const int buf = c % 3;
        if (c + 2 < ktiles) {
            uint32_t off = ((c + 2) % 3) * stB;
            load_tile16(sA + off, Ab, lda, (c + 2) * 16, tid);
            load_tile16(sB + off, Bb, ldb, (c + 2) * 16, tid);
            cp_commit();
            cp_wait2();
        } else if (c + 1 < ktiles) {
            cp_wait1();
        } else {
            cp_wait0();
        }
        __syncthreads();

        const float* A3 = sa + buf * TILEF;
        const float* B3 = sb + buf * TILEF;

        uint32_t ah[4][4], al[4][4];
#pragma unroll
        for (int mt = 0; mt < 4; mt++) {
            int rr = wm0 + mt * 16 + g;
            float2 p00 = *(const float2*)&A3[rr * SROW + 2 * t];
            float2 p10 = *(const float2*)&A3[(rr + 8) * SROW + 2 * t];
            float2 p01 = *(const float2*)&A3[rr * SROW + 8 + 2 * t];
            float2 p11 = *(const float2*)&A3[(rr + 8) * SROW + 8 + 2 * t];
            split_bf16x2(p00, ah[mt][0], al[mt][0]);
            split_bf16x2(p10, ah[mt][1], al[mt][1]);
            split_bf16x2(p01, ah[mt][2], al[mt][2]);
            split_bf16x2(p11, ah[mt][3], al[mt][3]);
        }
#pragma unroll
        for (int nt = 0; nt < 4; nt++) {
            int cc = wn0 + nt * 8 + g;
            float2 q0 = *(const float2*)&B3[cc * SROW + 2 * t];
            float2 q1 = *(const float2*)&B3[cc * SROW + 8 + 2 * t];
            uint32_t bh0, bl0, bh1, bl1;
            split_bf16x2(q0, bh0, bl0);
            split_bf16x2(q1, bh1, bl1);
#pragma unroll
            for (int mt = 0; mt < 4; mt++) {
                float* d = acc[mt][nt];
                MMA_BF16(d, ah[mt][0], ah[mt][1], ah[mt][2], ah[mt][3], bh0, bh1);
                MMA_BF16(d, ah[mt][0], ah[mt][1], ah[mt][2], ah[mt][3], bl0, bl1);
                MMA_BF16(d, al[mt][0], al[mt][1], al[mt][2], al[mt][3], bh0, bh1);
            }
        }
        __syncthreads();
    }
}

// Common projection epilogue: add bias, optional pad-zeroing, fp32 store.
__device__ __forceinline__ void proj_epilogue(
    float (&acc)[4][4][4], const float* __restrict__ bias,
    float* __restrict__ C, const int* __restrict__ pad,
    int m0, int n0, int tid)
{
    const int lane = tid & 31;
    const int warp = tid >> 5;
    const int g = lane >> 2, t = lane & 3;
    const int wm0 = (warp >> 2) * 64;
    const int wn0 = (warp & 3) * 32;

#pragma unroll
    for (int mt = 0; mt < 4; mt++) {
        int r0 = m0 + wm0 + mt * 16 + g;
        int r1 = r0 + 8;
        bool z0 = false, z1 = false;
        if (pad != nullptr) {
            z0 = ((r0 & 2047) >= MM - pad[r0 >> 11]);
            z1 = ((r1 & 2047) >= MM - pad[r1 >> 11]);
        }
#pragma unroll
        for (int nt = 0; nt < 4; nt++) {
            int col = n0 + wn0 + nt * 8 + 2 * t;
            float2 bi = *(const float2*)&bias[col];
            float* d = acc[mt][nt];
            float2 o0 = z0 ? make_float2(0.f, 0.f)
                           : make_float2(d[0] + bi.x, d[1] + bi.y);
            float2 o1 = z1 ? make_float2(0.f, 0.f)
                           : make_float2(d[2] + bi.x, d[3] + bi.y);
            *(float2*)&C[(size_t)r0 * DD + col] = o0;
            *(float2*)&C[(size_t)r1 * DD + col] = o1;
        }
    }
}

// ---------------------------------------------------------------------------
// Fused Q/K/V projection: grid (32, 24). Segment = blockIdx.y >> 3.
// ---------------------------------------------------------------------------
__global__ __launch_bounds__(256, 2) void qkv_mma(
    const float* __restrict__ q_in, const float* __restrict__ k_in,
    const float* __restrict__ v_in,
    const float* __restrict__ wq, const float* __restrict__ wk,
    const float* __restrict__ wv,
    const float* __restrict__ bq, const float* __restrict__ bk,
    const float* __restrict__ bv,
    const int* __restrict__ kpl)
{
    extern __shared__ float smem[];
    float* sa = smem;
    float* sb = smem + STAGES * TILEF;

    const int tid = threadIdx.x;
    const int seg = blockIdx.y >> 3;
    const int n0 = (blockIdx.y & 7) * 128;
    const int m0 = blockIdx.x * 128;

    const float* A    = (seg == 0) ? q_in : (seg == 1) ? k_in : v_in;
    const float* W    = (seg == 0) ? wq   : (seg == 1) ? wk   : wv;
    const float* bias = (seg == 0) ? bq   : (seg == 1) ? bk   : bv;
    float*       C    = (seg == 0) ? g_Q  : (seg == 1) ? g_K  : g_V;
    const int*   pad  = (seg == 1) ? kpl  : nullptr;

    float acc[4][4][4];
#pragma unroll
    for (int i = 0; i < 4; i++)
#pragma unroll
        for (int j = 0; j < 4; j++)
#pragma unroll
            for (int p = 0; p < 4; p++) acc[i][j][p] = 0.f;

    mma3_mainloop(A + (size_t)m0 * DD, DD, W + (size_t)n0 * DD, DD,
                  64, sa, sb, acc, tid);
    proj_epilogue(acc, bias, C, pad, m0, n0, tid);
}

// ---------------------------------------------------------------------------
// Output projection: C = A @ W^T + bias. Grid (32, 8).
// ---------------------------------------------------------------------------
__global__ __launch_bounds__(256, 2) void proj_mma(
    const float* __restrict__ A, const float* __restrict__ W,
    const float* __restrict__ bias, float* __restrict__ C)
{
    extern __shared__ float smem[];
    float* sa = smem;
    float* sb = smem + STAGES * TILEF;

    const int tid = threadIdx.x;
    const int m0 = blockIdx.x * 128;
    const int n0 = blockIdx.y * 128;

    float acc[4][4][4];
#pragma unroll
    for (int i = 0; i < 4; i++)
#pragma unroll
        for (int j = 0; j < 4; j++)
#pragma unroll
            for (int p = 0; p < 4; p++) acc[i][j][p] = 0.f;

    mma3_mainloop(A + (size_t)m0 * DD, DD, W + (size_t)n0 * DD, DD,
                  64, sa, sb, acc, tid);
    proj_epilogue(acc, bias, C, nullptr, m0, n0, tid);
}

// ---------------------------------------------------------------------------
// Scores: S[bh,n,m] = (Q·K) * SCALE, 128x128 tiles, K=64. Causal skip.
// ---------------------------------------------------------------------------
__global__ __launch_bounds__(256, 2) void scores_mma(const int* __restrict__ flag)
{
    const int mt = blockIdx.x, ntb = blockIdx.y, bh = blockIdx.z;
    if (flag[0] != 0 && mt > ntb) return;

    extern __shared__ float smem[];
    float* sa = smem;
    float* sb = smem + STAGES * TILEF;

    const int b = bh >> 4, h = bh & 15;
    const int n0 = ntb * 128, m0 = mt * 128;
    const int tid = threadIdx.x;

    float acc[4][4][4];
#pragma unroll
    for (int i = 0; i < 4; i++)
#pragma unroll
        for (int j = 0; j < 4; j++)
#pragma unroll
            for (int p = 0; p < 4; p++) acc[i][j][p] = 0.f;

    const float* Ab = g_Q + (size_t)b * NN * DD + (size_t)n0 * DD + h * HD;
    const float* Bb = g_K + (size_t)b * MM * DD + (size_t)m0 * DD + h * HD;

    mma3_mainloop(Ab, DD, Bb, DD, 4, sa, sb, acc, tid);

    const int lane = tid & 31;
    const int warp = tid >> 5;
    const int g = lane >> 2, t = lane & 3;
    const int wm0 = (warp >> 2) * 64;
    const int wn0 = (warp & 3) * 32;

    float* Sbase = g_S + (size_t)bh * NN * MM;
#pragma unroll
    for (int qt = 0; qt < 4; qt++) {
        int r0 = n0 + wm0 + qt * 16 + g;
        int r1 = r0 + 8;
#pragma unroll
        for (int kt = 0; kt < 4; kt++) {
            int col = m0 + wn0 + kt * 8 + 2 * t;
            float* d = acc[qt][kt];
            *(float2*)&Sbase[(size_t)r0 * MM + col] =
                make_float2(d[0] * SCALE, d[1] * SCALE);
            *(float2*)&Sbase[(size_t)r1 * MM + col] =
                make_float2(d[2] * SCALE, d[3] * SCALE);
        }
    }
}

// ---------------------------------------------------------------------------
// Fused softmax + head-mean. One block per (b, n), heavy rows first.
// For each head h: softmax the row in place (zero-pad to 128-boundary),
// accumulating the head-mean in registers. Then write wout row (full MM).
// ---------------------------------------------------------------------------
__global__ __launch_bounds__(256) void softmax_wmean(const int* __restrict__ flag,
                                                     float* __restrict__ wout)
{
    const int blk = blockIdx.x;                 // 0 .. BB*NN-1
    const int b = blk >> 11;
    const int n = NN - 1 - (blk & (NN - 1));    // heavy (large-n) rows first
    const int causal = (flag[0] != 0);
    const int len    = causal ? (n + 1) : MM;
    const int lenpad = causal ? min((((n >> 7) + 1) << 7), MM) : MM;
    const int tid = threadIdx.x;
    const float NEGINF = __int_as_float(0xff800000);

    __shared__ float red[8];
    float wacc[8];
#pragma unroll
    for (int k = 0; k < 8; k++) wacc[k] = 0.f;

    for (int h = 0; h < HH; h++) {
        float* row = g_S + (((size_t)(b * HH + h) * NN) + n) * MM;

        float vals[8];
        float mx = NEGINF;
#pragma unroll
        for (int k = 0; k < 8; k++) {
            int j = tid + k * 256;
            float s = (j < len) ? row[j] : NEGINF;
            vals[k] = s;
            mx = fmaxf(mx, s);
        }
#pragma unroll
        for (int o = 16; o > 0; o >>= 1)
            mx = fmaxf(mx, __shfl_xor_sync(0xffffffffu, mx, o));
        if ((tid & 31) == 0) red[tid >> 5] = mx;
        __syncthreads();
        float bm = red[0];
#pragma unroll
        for (int w = 1; w < 8; w++) bm = fmaxf(bm, red[w]);
        __syncthreads();

        float sum = 0.f;
#pragma unroll
        for (int k = 0; k < 8; k++) {
            vals[k] = expf(vals[k] - bm);     // exp(-inf) = 0 for padding
            sum += vals[k];
        }
#pragma unroll
        for (int o = 16; o > 0; o >>= 1)
            sum += __shfl_xor_sync(0xffffffffu, sum, o);
        if ((tid & 31) == 0) red[tid >> 5] = sum;
        __syncthreads();
        float tot = red[0];
#pragma unroll
        for (int w = 1; w < 8; w++) tot += red[w];
        __syncthreads();
        float inv = 1.0f / tot;

#pragma unroll
        for (int k = 0; k < 8; k++) {
            int j = tid + k * 256;
            float p = vals[k] * inv;
            wacc[k] += p;
            if (j < lenpad) row[j] = p;
        }
    }

    if (wout != nullptr) {
        float* orow = wout + ((size_t)b * NN + n) * MM;
#pragma unroll
        for (int k = 0; k < 8; k++) {
            int j = tid + k * 256;
            orow[j] = wacc[k] * (1.0f / HH);
        }
    }
}

// ---------------------------------------------------------------------------
// OV on tensor cores (R6) — heavy blocks (large ntb) scheduled first.
// ---------------------------------------------------------------------------
__global__ __launch_bounds__(256) void attn_ov(const int* __restrict__ flag)
{
    const int ntb = gridDim.x - 1 - blockIdx.x;   // heavy first
    const int bh = blockIdx.y;
    const int b = bh >> 4, h = bh & 15;
    const int n0 = ntb * 128;
    const int chunks = (flag[0] != 0) ? ((n0 + 128) >> 4) : (MM >> 4);

    __shared__ float Ps[2][128][SROW];
    __shared__ float Vs[2][16][68];

    const int tid = threadIdx.x;
    const int lane = tid & 31, warp = tid >> 5;
    const int g = lane >> 2, t = lane & 3;
    const int wy = warp >> 1;
    const int wx = warp & 1;

    const float* Pbase = g_S + ((size_t)bh * NN + n0) * MM;
    const float* Vbase = g_V + (size_t)b * MM * DD + h * HD;

    uint32_t sP = (uint32_t)__cvta_generic_to_shared(&Ps[0][0][0]);
    uint32_t sV = (uint32_t)__cvta_generic_to_shared(&Vs[0][0][0]);
    const uint32_t PstB = 128 * SROW * 4;
    const uint32_t VstB = 16 * 68 * 4;

    const int pr0 = tid >> 2,          pk0 = (tid & 3) * 4;
    const int pr1 = (tid + 256) >> 2,  pk1 = ((tid + 256) & 3) * 4;
    const int vrr = tid >> 4,          vcc = (tid & 15) * 4;

    float acc[2][4][4];
#pragma unroll
    for (int i = 0; i < 2; i++)
#pragma unroll
        for (int j = 0; j < 4; j++)
#pragma unroll
            for (int p = 0; p < 4; p++) acc[i][j][p] = 0.f;

    cp16(sP + (uint32_t)(pr0 * SROW + pk0) * 4, Pbase + (size_t)pr0 * MM + pk0);
    cp16(sP + (uint32_t)(pr1 * SROW + pk1) * 4, Pbase + (size_t)pr1 * MM + pk1);
    cp16(sV + (uint32_t)(vrr * 68 + vcc) * 4,   Vbase + (size_t)vrr * DD + vcc);
    cp_commit();

    for (int c = 0; c < chunks; c++) {
        const int buf = c & 1;
        if (c + 1 < chunks) {
            const int j0 = (c + 1) * 16;
            uint32_t op = (buf ^ 1) * PstB;
            uint32_t ov = (buf ^ 1) * VstB;
            cp16(sP + op + (uint32_t)(pr0 * SROW + pk0) * 4, Pbase + (size_t)pr0 * MM + j0 + pk0);
            cp16(sP + op + (uint32_t)(pr1 * SROW + pk1) * 4, Pbase + (size_t)pr1 * MM + j0 + pk1);
            cp16(sV + ov + (uint32_t)(vrr * 68 + vcc) * 4,   Vbase + (size_t)(j0 + vrr) * DD + vcc);
            cp_commit();
            cp_wait1();
        } else {
            cp_wait0();
        }
        __syncthreads();

        uint32_t ah[2][4], al[2][4];
#pragma unroll
        for (int mt = 0; mt < 2; mt++) {
            int rr = wy * 32 + mt * 16 + g;
            float2 p00 = *(const float2*)&Ps[buf][rr][2 * t];
            float2 p10 = *(const float2*)&Ps[buf][rr + 8][2 * t];
            float2 p01 = *(const float2*)&Ps[buf][rr][8 + 2 * t];
            float2 p11 = *(const float2*)&Ps[buf][rr + 8][8 + 2 * t];
            split_bf16x2(p00, ah[mt][0], al[mt][0]);
            split_bf16x2(p10, ah[mt][1], al[mt][1]);
            split_bf16x2(p01, ah[mt][2], al[mt][2]);
            split_bf16x2(p11, ah[mt][3], al[mt][3]);
        }
#pragma unroll
        for (int nt = 0; nt < 4; nt++) {
            int dd = wx * 32 + nt * 8 + g;
            float2 q0 = make_float2(Vs[buf][2 * t][dd],     Vs[buf][2 * t + 1][dd]);
            float2 q1 = make_float2(Vs[buf][8 + 2 * t][dd], Vs[buf][9 + 2 * t][dd]);
            uint32_t bh0, bl0, bh1, bl1;
            split_bf16x2(q0, bh0, bl0);
            split_bf16x2(q1, bh1, bl1);
#pragma unroll
            for (int mt = 0; mt < 2; mt++) {
                float* d = acc[mt][nt];
                MMA_BF16(d, ah[mt][0], ah[mt][1], ah[mt][2], ah[mt][3], bh0, bh1);
                MMA_BF16(d, ah[mt][0], ah[mt][1], ah[mt][2], ah[mt][3], bl0, bl1);
                MMA_BF16(d, al[mt][0], al[mt][1], al[mt][2], al[mt][3], bh0, bh1);
            }
        }
        __syncthreads();
    }

#pragma unroll
    for (int mt = 0; mt < 2; mt++) {
        int r0 = n0 + wy * 32 + mt * 16 + g;
        int r1 = r0 + 8;
#pragma unroll
        for (int nt = 0; nt < 4; nt++) {
            int col = h * HD + wx * 32 + nt * 8 + 2 * t;
            float* d = acc[mt][nt];
            *(float2*)&g_O[((size_t)b * NN + r0) * DD + col] = make_float2(d[0], d[1]);
            *(float2*)&g_O[((size_t)b * NN + r1) * DD + col] = make_float2(d[2], d[3]);
        }
    }
}

// ---------------------------------------------------------------------------
// Launch
// ---------------------------------------------------------------------------
extern "C" void kernel_launch(void* const* d_in, const int* in_sizes, int n_in,
                              void* d_out, int out_size)
{
    const float* query = (const float*)d_in[0];
    const float* key   = (const float*)d_in[1];
    const float* value = (const float*)d_in[2];
    const int*   kpl   = (const int*)d_in[3];
    const int*   flag  = (const int*)d_in[4];
    const float* wq_w  = (const float*)d_in[5];
    const float* wq_b  = (const float*)d_in[6];
    const float* wk_w  = (const float*)d_in[7];
    const float* wk_b  = (const float*)d_in[8];
    const float* wv_w  = (const float*)d_in[9];
    const float* wv_b  = (const float*)d_in[10];
    const float* wo_w  = (const float*)d_in[11];
    const float* wo_b  = (const float*)d_in[12];
    float* out = (float*)d_out;

    static bool attr_done = false;
    if (!attr_done) {
        cudaFuncSetAttribute(qkv_mma,    cudaFuncAttributeMaxDynamicSharedMemorySize, SMEMB);
        cudaFuncSetAttribute(proj_mma,   cudaFuncAttributeMaxDynamicSharedMemorySize, SMEMB);
        cudaFuncSetAttribute(scores_mma, cudaFuncAttributeMaxDynamicSharedMemorySize, SMEMB);
        attr_done = true;
    }

    float *Op;
    cudaGetSymbolAddress((void**)&Op, g_O);

    qkv_mma<<<dim3(32, 24), 256, SMEMB>>>(query, key, value,
                                          wq_w, wk_w, wv_w,
                                          wq_b, wk_b, wv_b, kpl);

    scores_mma<<<dim3(16, 16, 32), 256, SMEMB>>>(flag);

    const long long need = (long long)BB * NN * DD + (long long)BB * NN * MM;
    float* wout = ((long long)out_size >= need) ? (out + (size_t)BB * NN * DD)
                                                : nullptr;
    softmax_wmean<<<BB * NN, 256>>>(flag, wout);

    attn_ov<<<dim3(16, 32), 256>>>(flag);

    proj_mma<<<dim3(32, 8), 256, SMEMB>>>(Op, wo_w, wo_b, out);
}